// round 6
// baseline (speedup 1.0000x reference)
#include <cuda_runtime.h>
#include <cstdint>

#define SDIM 1024
#define BHN  64
#define THREADS 128
#define SLOT_BYTES 32768              /* A: 16KB (128x32 tf32) + B: 16KB (32x128) */
#define SMEM_BYTES (2 * SLOT_BYTES)   /* 64KB, double buffered */

// 256 MB scratch for attention probabilities.
__device__ __align__(16) float g_attn[(size_t)BHN * SDIM * SDIM];

__device__ __forceinline__ uint32_t f2tf(float x) {
    uint32_t r;
    asm("cvt.rna.tf32.f32 %0, %1;" : "=r"(r) : "f"(x));
    return r;
}

__device__ __forceinline__ uint32_t smem_u32(const void* p) {
    uint32_t a;
    asm("{ .reg .u64 t; cvta.to.shared.u64 t, %1; cvt.u32.u64 %0, t; }"
        : "=r"(a) : "l"(p));
    return a;
}

__device__ __forceinline__ void ldsm4(uint32_t a[4], uint32_t addr) {
    asm volatile("ldmatrix.sync.aligned.m8n8.x4.shared.b16 {%0,%1,%2,%3}, [%4];"
        : "=r"(a[0]), "=r"(a[1]), "=r"(a[2]), "=r"(a[3]) : "r"(addr));
}

__device__ __forceinline__ uint32_t lds32(uint32_t addr) {
    uint32_t v;
    asm volatile("ld.shared.b32 %0, [%1];" : "=r"(v) : "r"(addr));
    return v;
}

__device__ __forceinline__ void mma_tf32(float c[4], const uint32_t a[4],
                                         uint32_t b0, uint32_t b1) {
    asm volatile(
        "mma.sync.aligned.m16n8k8.row.col.f32.tf32.tf32.f32 "
        "{%0,%1,%2,%3}, {%4,%5,%6,%7}, {%8,%9}, {%0,%1,%2,%3};"
        : "+f"(c[0]), "+f"(c[1]), "+f"(c[2]), "+f"(c[3])
        : "r"(a[0]), "r"(a[1]), "r"(a[2]), "r"(a[3]), "r"(b0), "r"(b1));
}

// CTA tile 128x128, 4 warps (2x2), warp tile 64x64, mma m16n8k8 tf32.
// A smem: [m][32w] 128B rows, 16B-chunk swizzle ch^(m&7)  -> ldmatrix.x4 reads.
// B smem: [k][128w] 512B rows, word swizzle n^((k&7)<<3) -> conflict-free LDS.32.
// fuse_epi=1: out = (acc + AddM)*scale + Mask  (QK -> g_attn); 0: out = acc.
__global__ __launch_bounds__(THREADS, 2) void gemm_kernel(
    const float* __restrict__ Ag, const float* __restrict__ Bg,
    const float* __restrict__ AddM, const float* __restrict__ Mask,
    float* __restrict__ Out, int fuse_epi)
{
    extern __shared__ __align__(128) char smem[];
    const uint32_t sbase = smem_u32(smem);

    const int bm = blockIdx.x, bn = blockIdx.y, bh = blockIdx.z;
    const int tid  = threadIdx.x;
    const int warp = tid >> 5, lane = tid & 31;
    const int wm = warp >> 1, wn = warp & 1;   // 2 x 2 warp grid
    const int lr = lane >> 2, lc = lane & 3;

    const size_t mat = (size_t)bh * SDIM * SDIM;
    const float* Abase = Ag + mat + (size_t)(bm * 128) * SDIM;
    const float* Bbase = Bg + mat + bn * 128;

    // Per-thread fill coordinates (8 float4 each for A and B).
    const int a_m  = tid >> 3;            // rows handled: a_m + 16*i? no: idx=tid+i*128
    const int a_ch = tid & 7;
    (void)a_m; (void)a_ch;

    float c[4][8][4];
    #pragma unroll
    for (int i = 0; i < 4; i++)
        #pragma unroll
        for (int j = 0; j < 8; j++)
            #pragma unroll
            for (int r = 0; r < 4; r++) c[i][j][r] = 0.f;

    // A fragment geometry (ldmatrix): verified in round 3.
    const int moff = ((lane >> 3) & 1) * 8 + (lane & 7);
    const int csel = lane >> 4;
    uint32_t a_base[4];  // byte offset of row m within A tile, plus m&7 packed
    int      a_m7[4];
    #pragma unroll
    for (int ti = 0; ti < 4; ti++) {
        int m = wm * 64 + ti * 16 + moff;
        a_base[ti] = (uint32_t)m * 128u;
        a_m7[ti]   = m & 7;
    }
    // B fragment geometry: lane holds n = wn*64 + tj*8 + lr, k = kk + lc (+4).
    uint32_t nxb[8];     // byte offset of swizzled word n within a k-row
    #pragma unroll
    for (int tj = 0; tj < 8; tj++) {
        int n = wn * 64 + tj * 8 + lr;
        nxb[tj] = (uint32_t)((n ^ (lc << 3)) << 2);
    }

    // ---- fill one slot (A tile 128x32, B tile 32x128) at k-offset kt ----
    auto fill = [&](int slot, int kt) {
        char* sA = smem + slot * SLOT_BYTES;
        char* sB = sA + 16384;
        #pragma unroll
        for (int i = 0; i < 4; ++i) {       // A: 1024 float4 / 128 thr, 2 per iter pair
            int idx = tid + i * 256;
            int r0 = idx >> 3, ch0 = idx & 7;
            int idx2 = idx + 128;
            int r1 = idx2 >> 3, ch1 = idx2 & 7;
            float4 v0 = *reinterpret_cast<const float4*>(Abase + (size_t)r0 * SDIM + kt + ch0 * 4);
            float4 v1 = *reinterpret_cast<const float4*>(Abase + (size_t)r1 * SDIM + kt + ch1 * 4);
            uint4 u0, u1;
            u0.x = f2tf(v0.x); u0.y = f2tf(v0.y); u0.z = f2tf(v0.z); u0.w = f2tf(v0.w);
            u1.x = f2tf(v1.x); u1.y = f2tf(v1.y); u1.z = f2tf(v1.z); u1.w = f2tf(v1.w);
            *reinterpret_cast<uint4*>(sA + r0 * 128 + ((ch0 ^ (r0 & 7)) << 4)) = u0;
            *reinterpret_cast<uint4*>(sA + r1 * 128 + ((ch1 ^ (r1 & 7)) << 4)) = u1;
        }
        #pragma unroll
        for (int i = 0; i < 4; ++i) {       // B: 1024 float4 / 128 thr
            int idx = tid + i * 256;
            int k0 = idx >> 5, nq0 = (idx & 31) << 2;
            int idx2 = idx + 128;
            int k1 = idx2 >> 5, nq1 = (idx2 & 31) << 2;
            float4 v0 = *reinterpret_cast<const float4*>(Bbase + (size_t)(kt + k0) * SDIM + nq0);
            float4 v1 = *reinterpret_cast<const float4*>(Bbase + (size_t)(kt + k1) * SDIM + nq1);
            uint4 u0, u1;
            u0.x = f2tf(v0.x); u0.y = f2tf(v0.y); u0.z = f2tf(v0.z); u0.w = f2tf(v0.w);
            u1.x = f2tf(v1.x); u1.y = f2tf(v1.y); u1.z = f2tf(v1.z); u1.w = f2tf(v1.w);
            *reinterpret_cast<uint4*>(sB + k0 * 512 + ((nq0 ^ ((k0 & 7) << 3)) << 2)) = u0;
            *reinterpret_cast<uint4*>(sB + k1 * 512 + ((nq1 ^ ((k1 & 7) << 3)) << 2)) = u1;
        }
    };

    // ---- compute one slot ----
    auto compute = [&](int slot) {
        const uint32_t sA = sbase + slot * SLOT_BYTES;
        const uint32_t sB = sA + 16384;
        #pragma unroll
        for (int kk4 = 0; kk4 < 4; ++kk4) {          // kk = kk4*8
            const int kk = kk4 << 3;
            uint32_t af[4][4];
            const int chunk = (kk >> 2) + csel;
            #pragma unroll
            for (int ti = 0; ti < 4; ++ti)
                ldsm4(af[ti], sA + a_base[ti] + (uint32_t)((chunk ^ a_m7[ti]) << 4));

            uint32_t b0[8], b1[8];
            const uint32_t row0 = sB + (uint32_t)(kk + lc) * 512u;
            const uint32_t row1 = row0 + 2048u;
            #pragma unroll
            for (int tj = 0; tj < 8; ++tj) {
                b0[tj] = lds32(row0 + nxb[tj]);
                b1[tj] = lds32(row1 + (nxb[tj] ^ 128u));
            }
            #pragma unroll
            for (int ti = 0; ti < 4; ++ti)
                #pragma unroll
                for (int tj = 0; tj < 8; ++tj)
                    mma_tf32(c[ti][tj], af[ti], b0[tj], b1[tj]);
        }
    };

    fill(0, 0);
    __syncthreads();
    #pragma unroll 1
    for (int it = 0; it < 32; ++it) {
        const int slot = it & 1;
        if (it < 31) fill(slot ^ 1, (it + 1) << 5);
        compute(slot);
        __syncthreads();
    }

    // ---- epilogue ----
    const float scale = 0.03125f;  // 1/sqrt(1024)
    #pragma unroll
    for (int ti = 0; ti < 4; ti++) {
        #pragma unroll
        for (int tj = 0; tj < 8; tj++) {
            int i0 = bm * 128 + wm * 64 + ti * 16 + lr;
            int j0 = bn * 128 + wn * 64 + tj * 8 + lc * 2;
            #pragma unroll
            for (int h = 0; h < 2; h++) {
                int i = i0 + h * 8;
                float v0 = c[ti][tj][h * 2 + 0];
                float v1 = c[ti][tj][h * 2 + 1];
                size_t off = mat + (size_t)i * SDIM + j0;
                if (fuse_epi) {
                    float2 bb = *reinterpret_cast<const float2*>(AddM + off);
                    float2 mm = *reinterpret_cast<const float2*>(
                        Mask + (size_t)i * SDIM + j0);
                    v0 = (v0 + bb.x) * scale + mm.x;
                    v1 = (v1 + bb.y) * scale + mm.y;
                }
                float2 o; o.x = v0; o.y = v1;
                *reinterpret_cast<float2*>(Out + off) = o;
            }
        }
    }
}

// One CTA (256 threads) per row of 1024; in-place softmax on g_attn.
__global__ __launch_bounds__(256) void softmax_kernel() {
    const size_t row = blockIdx.x;
    float* p = g_attn + row * SDIM;
    const int tid = threadIdx.x;
    const int warp = tid >> 5, lane = tid & 31;
    __shared__ float sred[8];

    float4 v = reinterpret_cast<float4*>(p)[tid];

    float m = fmaxf(fmaxf(v.x, v.y), fmaxf(v.z, v.w));
    #pragma unroll
    for (int o = 16; o; o >>= 1) m = fmaxf(m, __shfl_xor_sync(0xffffffffu, m, o));
    if (lane == 0) sred[warp] = m;
    __syncthreads();
    m = sred[0];
    #pragma unroll
    for (int i = 1; i < 8; i++) m = fmaxf(m, sred[i]);
    __syncthreads();

    v.x = expf(v.x - m);
    v.y = expf(v.y - m);
    v.z = expf(v.z - m);
    v.w = expf(v.w - m);
    float s = v.x + v.y + v.z + v.w;
    #pragma unroll
    for (int o = 16; o; o >>= 1) s += __shfl_xor_sync(0xffffffffu, s, o);
    if (lane == 0) sred[warp] = s;
    __syncthreads();
    s = sred[0];
    #pragma unroll
    for (int i = 1; i < 8; i++) s += sred[i];

    float inv = 1.0f / s;
    v.x *= inv; v.y *= inv; v.z *= inv; v.w *= inv;
    reinterpret_cast<float4*>(p)[tid] = v;
}

extern "C" void kernel_launch(void* const* d_in, const int* in_sizes, int n_in,
                              void* d_out, int out_size) {
    const float* A    = (const float*)d_in[0];
    const float* J    = (const float*)d_in[1];
    const float* B    = (const float*)d_in[2];
    const float* P    = (const float*)d_in[3];
    const float* mask = (const float*)d_in[4];
    float* out = (float*)d_out;

    float* attn = nullptr;
    cudaGetSymbolAddress((void**)&attn, g_attn);

    cudaFuncSetAttribute(gemm_kernel, cudaFuncAttributeMaxDynamicSharedMemorySize,
                         SMEM_BYTES);

    dim3 grid(SDIM / 128, SDIM / 128, BHN);  // 8 x 8 x 64
    gemm_kernel<<<grid, THREADS, SMEM_BYTES>>>(A, J, B, mask, attn, 1);
    softmax_kernel<<<BHN * SDIM, 256>>>();
    gemm_kernel<<<grid, THREADS, SMEM_BYTES>>>(attn, P, nullptr, nullptr, out, 0);
}

// round 7
// speedup vs baseline: 1.0114x; 1.0114x over previous
#include <cuda_runtime.h>
#include <cstdint>

#define SDIM 1024
#define BHN  64
#define THREADS 256
#define SLOT_BYTES 32768              /* A: 16KB (128x32 tf32) + B: 16KB (32x128) */
#define SMEM_BYTES (2 * SLOT_BYTES)   /* 64KB, double buffered */

// 256 MB scratch for attention probabilities.
__device__ __align__(16) float g_attn[(size_t)BHN * SDIM * SDIM];

__device__ __forceinline__ uint32_t f2tf(float x) {
    uint32_t r;
    asm("cvt.rna.tf32.f32 %0, %1;" : "=r"(r) : "f"(x));
    return r;
}

__device__ __forceinline__ uint32_t smem_u32(const void* p) {
    uint32_t a;
    asm("{ .reg .u64 t; cvta.to.shared.u64 t, %1; cvt.u32.u64 %0, t; }"
        : "=r"(a) : "l"(p));
    return a;
}

__device__ __forceinline__ void ldsm4(uint32_t a[4], uint32_t addr) {
    asm volatile("ldmatrix.sync.aligned.m8n8.x4.shared.b16 {%0,%1,%2,%3}, [%4];"
        : "=r"(a[0]), "=r"(a[1]), "=r"(a[2]), "=r"(a[3]) : "r"(addr));
}

__device__ __forceinline__ uint32_t lds32(uint32_t addr) {
    uint32_t v;
    asm volatile("ld.shared.b32 %0, [%1];" : "=r"(v) : "r"(addr));
    return v;
}

__device__ __forceinline__ void mma_tf32(float c[4], const uint32_t a[4],
                                         uint32_t b0, uint32_t b1) {
    asm volatile(
        "mma.sync.aligned.m16n8k8.row.col.f32.tf32.tf32.f32 "
        "{%0,%1,%2,%3}, {%4,%5,%6,%7}, {%8,%9}, {%0,%1,%2,%3};"
        : "+f"(c[0]), "+f"(c[1]), "+f"(c[2]), "+f"(c[3])
        : "r"(a[0]), "r"(a[1]), "r"(a[2]), "r"(a[3]), "r"(b0), "r"(b1));
}

// CTA tile 128x128, 8 warps (2x4), warp tile 64x32, mma m16n8k8 tf32.
// A smem: [m][32w] 128B rows, 16B-chunk swizzle ch^(m&7)  -> ldmatrix.x4 reads.
// B smem: [k][128w] 512B rows, word swizzle n^((k&7)<<3)  -> conflict-free LDS.32.
// fuse_epi=1: out = (acc + AddM)*scale + Mask  (QK -> g_attn); 0: out = acc.
__global__ __launch_bounds__(THREADS, 2) void gemm_kernel(
    const float* __restrict__ Ag, const float* __restrict__ Bg,
    const float* __restrict__ AddM, const float* __restrict__ Mask,
    float* __restrict__ Out, int fuse_epi)
{
    extern __shared__ __align__(128) char smem[];
    const uint32_t sbase = smem_u32(smem);

    const int bm = blockIdx.x, bn = blockIdx.y, bh = blockIdx.z;
    const int tid  = threadIdx.x;
    const int warp = tid >> 5, lane = tid & 31;
    const int wm = warp >> 2, wn = warp & 3;   // 2 x 4 warp grid
    const int lr = lane >> 2, lc = lane & 3;

    const size_t mat = (size_t)bh * SDIM * SDIM;
    const float* Abase = Ag + mat + (size_t)(bm * 128) * SDIM;
    const float* Bbase = Bg + mat + bn * 128;

    float c[4][4][4];
    #pragma unroll
    for (int i = 0; i < 4; i++)
        #pragma unroll
        for (int j = 0; j < 4; j++)
            #pragma unroll
            for (int r = 0; r < 4; r++) c[i][j][r] = 0.f;

    // A fragment geometry (ldmatrix), verified rounds 3/5.
    const int moff = ((lane >> 3) & 1) * 8 + (lane & 7);
    const int csel = lane >> 4;
    uint32_t a_base[4];
    int      a_m7[4];
    #pragma unroll
    for (int ti = 0; ti < 4; ti++) {
        int m = wm * 64 + ti * 16 + moff;
        a_base[ti] = (uint32_t)m * 128u;
        a_m7[ti]   = m & 7;
    }
    // B fragment geometry: lane holds n = wn*32 + tj*8 + lr, k = kk + lc (+4).
    uint32_t nxb[4];
    #pragma unroll
    for (int tj = 0; tj < 4; tj++) {
        int n = wn * 32 + tj * 8 + lr;
        nxb[tj] = (uint32_t)((n ^ (lc << 3)) << 2);
    }

    // Per-thread fill coordinates (256 threads: 4 float4 each for A and B).
    const int fa_r  = tid >> 3;          // A row for i-th iter: fa_r + 0 (idx=tid+i*256 -> r=idx>>3)
    const int fa_ch = tid & 7;
    const int fb_k  = tid >> 5;
    const int fb_nq = (tid & 31) << 2;

    // ---- fill one slot (A tile 128x32, B tile 32x128) at k-offset kt ----
    auto fill = [&](int slot, int kt) {
        char* sA = smem + slot * SLOT_BYTES;
        char* sB = sA + 16384;
        #pragma unroll
        for (int i = 0; i < 4; ++i) {            // A: 1024 float4 / 256 thr
            int r  = fa_r + i * 32;
            float4 v = *reinterpret_cast<const float4*>(
                Abase + (size_t)r * SDIM + kt + fa_ch * 4);
            uint4 u;
            u.x = f2tf(v.x); u.y = f2tf(v.y); u.z = f2tf(v.z); u.w = f2tf(v.w);
            *reinterpret_cast<uint4*>(sA + r * 128 + ((fa_ch ^ (r & 7)) << 4)) = u;
        }
        #pragma unroll
        for (int i = 0; i < 4; ++i) {            // B: 1024 float4 / 256 thr
            int k  = fb_k + i * 8;
            float4 v = *reinterpret_cast<const float4*>(
                Bbase + (size_t)(kt + k) * SDIM + fb_nq);
            uint4 u;
            u.x = f2tf(v.x); u.y = f2tf(v.y); u.z = f2tf(v.z); u.w = f2tf(v.w);
            *reinterpret_cast<uint4*>(sB + k * 512 + ((fb_nq ^ ((k & 7) << 3)) << 2)) = u;
        }
    };

    // ---- compute one slot ----
    auto compute = [&](int slot) {
        const uint32_t sA = sbase + slot * SLOT_BYTES;
        const uint32_t sB = sA + 16384;
        #pragma unroll
        for (int kk4 = 0; kk4 < 4; ++kk4) {
            const int kk = kk4 << 3;
            uint32_t af[4][4];
            const int chunk = (kk4 << 1) + csel;
            #pragma unroll
            for (int ti = 0; ti < 4; ++ti)
                ldsm4(af[ti], sA + a_base[ti] + (uint32_t)((chunk ^ a_m7[ti]) << 4));

            uint32_t b0[4], b1[4];
            const uint32_t row0 = sB + (uint32_t)(kk + lc) * 512u;
            const uint32_t row1 = row0 + 2048u;
            #pragma unroll
            for (int tj = 0; tj < 4; ++tj) {
                b0[tj] = lds32(row0 + nxb[tj]);
                b1[tj] = lds32(row1 + (nxb[tj] ^ 128u));
            }
            #pragma unroll
            for (int ti = 0; ti < 4; ++ti)
                #pragma unroll
                for (int tj = 0; tj < 4; ++tj)
                    mma_tf32(c[ti][tj], af[ti], b0[tj], b1[tj]);
        }
    };

    fill(0, 0);
    __syncthreads();
    #pragma unroll 1
    for (int it = 0; it < 32; ++it) {
        const int slot = it & 1;
        if (it < 31) fill(slot ^ 1, (it + 1) << 5);
        compute(slot);
        __syncthreads();
    }

    // ---- epilogue ----
    const float scale = 0.03125f;  // 1/sqrt(1024)
    #pragma unroll
    for (int ti = 0; ti < 4; ti++) {
        #pragma unroll
        for (int tj = 0; tj < 4; tj++) {
            int i0 = bm * 128 + wm * 64 + ti * 16 + lr;
            int j0 = bn * 128 + wn * 32 + tj * 8 + lc * 2;
            #pragma unroll
            for (int h = 0; h < 2; h++) {
                int i = i0 + h * 8;
                float v0 = c[ti][tj][h * 2 + 0];
                float v1 = c[ti][tj][h * 2 + 1];
                size_t off = mat + (size_t)i * SDIM + j0;
                if (fuse_epi) {
                    float2 bb = *reinterpret_cast<const float2*>(AddM + off);
                    float2 mm = *reinterpret_cast<const float2*>(
                        Mask + (size_t)i * SDIM + j0);
                    v0 = (v0 + bb.x) * scale + mm.x;
                    v1 = (v1 + bb.y) * scale + mm.y;
                }
                float2 o; o.x = v0; o.y = v1;
                *reinterpret_cast<float2*>(Out + off) = o;
            }
        }
    }
}

// One CTA (256 threads) per row of 1024; in-place softmax on g_attn.
__global__ __launch_bounds__(256) void softmax_kernel() {
    const size_t row = blockIdx.x;
    float* p = g_attn + row * SDIM;
    const int tid = threadIdx.x;
    const int warp = tid >> 5, lane = tid & 31;
    __shared__ float sred[8];

    float4 v = reinterpret_cast<float4*>(p)[tid];

    float m = fmaxf(fmaxf(v.x, v.y), fmaxf(v.z, v.w));
    #pragma unroll
    for (int o = 16; o; o >>= 1) m = fmaxf(m, __shfl_xor_sync(0xffffffffu, m, o));
    if (lane == 0) sred[warp] = m;
    __syncthreads();
    m = sred[0];
    #pragma unroll
    for (int i = 1; i < 8; i++) m = fmaxf(m, sred[i]);
    __syncthreads();

    v.x = expf(v.x - m);
    v.y = expf(v.y - m);
    v.z = expf(v.z - m);
    v.w = expf(v.w - m);
    float s = v.x + v.y + v.z + v.w;
    #pragma unroll
    for (int o = 16; o; o >>= 1) s += __shfl_xor_sync(0xffffffffu, s, o);
    if (lane == 0) sred[warp] = s;
    __syncthreads();
    s = sred[0];
    #pragma unroll
    for (int i = 1; i < 8; i++) s += sred[i];

    float inv = 1.0f / s;
    v.x *= inv; v.y *= inv; v.z *= inv; v.w *= inv;
    reinterpret_cast<float4*>(p)[tid] = v;
}

extern "C" void kernel_launch(void* const* d_in, const int* in_sizes, int n_in,
                              void* d_out, int out_size) {
    const float* A    = (const float*)d_in[0];
    const float* J    = (const float*)d_in[1];
    const float* B    = (const float*)d_in[2];
    const float* P    = (const float*)d_in[3];
    const float* mask = (const float*)d_in[4];
    float* out = (float*)d_out;

    float* attn = nullptr;
    cudaGetSymbolAddress((void**)&attn, g_attn);

    cudaFuncSetAttribute(gemm_kernel, cudaFuncAttributeMaxDynamicSharedMemorySize,
                         SMEM_BYTES);

    dim3 grid(SDIM / 128, SDIM / 128, BHN);  // 8 x 8 x 64
    gemm_kernel<<<grid, THREADS, SMEM_BYTES>>>(A, J, B, mask, attn, 1);
    softmax_kernel<<<BHN * SDIM, 256>>>();
    gemm_kernel<<<grid, THREADS, SMEM_BYTES>>>(attn, P, nullptr, nullptr, out, 0);
}